// round 1
// baseline (speedup 1.0000x reference)
#include <cuda_runtime.h>
#include <math.h>

#define BMSZ 32
#define LSEQ 2048
#define NP   256
#define DM   128
#define DI   256
#define DS   16
#define DTR  8
#define PLEN 96
#define KH   (NP*DM)   /* 32768 */
#define EPSF 1e-5f

// -------- scratch (device globals; no allocation) --------
__device__ float g_mean[BMSZ];
__device__ float g_std[BMSZ];
__device__ float g_rstd[BMSZ];
__device__ float g_u[BMSZ*NP*DM];        // residual stream (4 MB)
__device__ float g_xb[BMSZ*NP*DI];       // 8 MB
__device__ float g_z[BMSZ*NP*DI];        // 8 MB
__device__ float g_xs[BMSZ*NP*DI];       // 8 MB
__device__ float g_delta[BMSZ*NP*DI];    // 8 MB
__device__ float g_bc[BMSZ*NP*32];       // B(16) then C(16) per token, 1 MB
__device__ float g_y[BMSZ*NP*DI];        // 8 MB
__device__ float g_part[128*BMSZ*PLEN];  // split-K head partials

__device__ __forceinline__ float siluf(float x) { return x / (1.f + __expf(-x)); }

// -------- K0: per-sequence mean/std over L --------
__global__ void k_stats(const float* __restrict__ x) {
    int bm = blockIdx.x, tid = threadIdx.x;
    float s = 0.f, s2 = 0.f;
    for (int i = tid; i < LSEQ; i += 256) {
        float v = x[bm*LSEQ + i];
        s += v; s2 += v*v;
    }
    __shared__ float sa[256], sb[256];
    sa[tid] = s; sb[tid] = s2; __syncthreads();
    for (int off = 128; off > 0; off >>= 1) {
        if (tid < off) { sa[tid] += sa[tid+off]; sb[tid] += sb[tid+off]; }
        __syncthreads();
    }
    if (tid == 0) {
        float m = sa[0] * (1.f/LSEQ);
        float var = sb[0] * (1.f/LSEQ) - m*m;
        float st = sqrtf(var + EPSF);
        g_mean[bm] = m; g_std[bm] = st; g_rstd[bm] = 1.f/st;
    }
}

// -------- K1: patch embedding: u = patches @ W_pe + b_pe + pos --------
__global__ void k_embed(const float* __restrict__ x, const float* __restrict__ W_pe,
                        const float* __restrict__ b_pe, const float* __restrict__ pos) {
    int p = blockIdx.x, bm = blockIdx.y, j = threadIdx.x;  // 128 threads
    __shared__ float sp[16];
    if (j < 16) {
        int t = p*8 + j; if (t > LSEQ-1) t = LSEQ-1;       // right-pad with last value
        sp[j] = (x[bm*LSEQ + t] - g_mean[bm]) * g_rstd[bm];
    }
    __syncthreads();
    float acc = b_pe[j] + pos[p*DM + j];
    #pragma unroll
    for (int k = 0; k < 16; k++) acc = fmaf(sp[k], W_pe[k*DM + j], acc);
    g_u[(bm*NP + p)*DM + j] = acc;
}

// -------- K2: RMSNorm + GEMM (rows x 128) @ (128 x 512) -> xb, z --------
__global__ void k_in(const float* __restrict__ rms_w, const float* __restrict__ W_in) {
    int row0 = blockIdx.x * 16, tid = threadIdx.x;   // 256 threads, 16 rows/block
    __shared__ float sh[16][128];
    __shared__ float ssc[16];
    for (int i = tid; i < 2048; i += 256) sh[i>>7][i&127] = g_u[row0*DM + i];
    __syncthreads();
    int w = tid >> 5, lane = tid & 31;
    #pragma unroll
    for (int rr = 0; rr < 2; rr++) {
        int r = w*2 + rr;
        float ss = 0.f;
        #pragma unroll
        for (int q = 0; q < 4; q++) { float v = sh[r][lane + 32*q]; ss += v*v; }
        #pragma unroll
        for (int o = 16; o > 0; o >>= 1) ss += __shfl_xor_sync(0xffffffffu, ss, o);
        if (lane == 0) ssc[r] = rsqrtf(ss * (1.f/128.f) + EPSF);
    }
    __syncthreads();
    for (int i = tid; i < 2048; i += 256) {
        int r = i>>7, k = i&127;
        sh[r][k] *= ssc[r] * rms_w[k];
    }
    __syncthreads();
    float a0[16], a1[16];
    #pragma unroll
    for (int r = 0; r < 16; r++) { a0[r] = 0.f; a1[r] = 0.f; }
    for (int k = 0; k < 128; k++) {
        float w0 = W_in[k*512 + tid];
        float w1 = W_in[k*512 + tid + 256];
        #pragma unroll
        for (int r = 0; r < 16; r++) {
            float v = sh[r][k];
            a0[r] = fmaf(v, w0, a0[r]);
            a1[r] = fmaf(v, w1, a1[r]);
        }
    }
    #pragma unroll
    for (int r = 0; r < 16; r++) {
        g_xb[(row0+r)*DI + tid] = a0[r];
        g_z [(row0+r)*DI + tid] = a1[r];
    }
}

// -------- K3: causal depthwise conv (width 4) + bias + SiLU --------
__global__ void k_conv(const float* __restrict__ conv_w, const float* __restrict__ conv_b) {
    int t = blockIdx.x, bm = blockIdx.y, c = threadIdx.x;   // 256 threads
    float4 cw = reinterpret_cast<const float4*>(conv_w)[c];
    float acc = conv_b[c];
    int base = bm*NP*DI + c;
    if (t >= 3) acc = fmaf(g_xb[base + (t-3)*DI], cw.x, acc);
    if (t >= 2) acc = fmaf(g_xb[base + (t-2)*DI], cw.y, acc);
    if (t >= 1) acc = fmaf(g_xb[base + (t-1)*DI], cw.z, acc);
    acc = fmaf(g_xb[base + t*DI], cw.w, acc);
    g_xs[base + t*DI] = siluf(acc);
}

// -------- K4: dbc = xs @ W_xp (256x40); delta = softplus(dbc[:,:8] @ W_dt + b_dt); stash B,C --------
__global__ void k_dbc(const float* __restrict__ W_xp, const float* __restrict__ W_dt,
                      const float* __restrict__ b_dt) {
    int tok0 = blockIdx.x * 32, tid = threadIdx.x;   // 256 threads, 32 tokens/block
    __shared__ float sxs[32*257];                    // padded to kill bank conflicts
    __shared__ float sdbc[32*40];
    for (int i = tid; i < 8192; i += 256) {
        int tt = i >> 8, k = i & 255;
        sxs[tt*257 + k] = g_xs[(tok0+tt)*DI + k];
    }
    __syncthreads();
    int o8 = tid & 7, tt = tid >> 3;                 // 32 tokens x 8 outputs -> 5 rounds
    for (int oo = 0; oo < 5; oo++) {
        int o = oo*8 + o8;
        float acc = 0.f;
        for (int k = 0; k < 256; k++) acc = fmaf(sxs[tt*257 + k], W_xp[k*40 + o], acc);
        sdbc[tt*40 + o] = acc;
    }
    __syncthreads();
    float wdt[8];
    #pragma unroll
    for (int r = 0; r < 8; r++) wdt[r] = W_dt[r*DI + tid];
    float bd = b_dt[tid];
    for (int t2 = 0; t2 < 32; t2++) {
        float acc = bd;
        #pragma unroll
        for (int r = 0; r < 8; r++) acc = fmaf(sdbc[t2*40 + r], wdt[r], acc);
        float dl = (acc > 20.f) ? acc : log1pf(__expf(acc));
        g_delta[(tok0+t2)*DI + tid] = dl;
    }
    for (int i = tid; i < 1024; i += 256) {
        int t2 = i >> 5, v = i & 31;
        g_bc[(tok0+t2)*32 + v] = sdbc[t2*40 + 8 + v];
    }
}

// -------- K5: selective scan. One thread per (seq, channel), 16 states in regs --------
__global__ void k_scan(const float* __restrict__ A_log, const float* __restrict__ D_ssm) {
    int bm = blockIdx.x, d = threadIdx.x;            // 32 blocks x 256 threads
    float Aa[16];
    #pragma unroll
    for (int s = 0; s < 16; s++) Aa[s] = -__expf(A_log[d*16 + s]);
    float Dd = D_ssm[d];
    float h[16];
    #pragma unroll
    for (int s = 0; s < 16; s++) h[s] = 0.f;
    int tb = bm*NP*DI + d;
    const float* bcb = g_bc + bm*NP*32;
    for (int t = 0; t < NP; t++) {
        float dlt = g_delta[tb + t*DI];
        float xv  = g_xs  [tb + t*DI];
        const float4* p4 = reinterpret_cast<const float4*>(bcb + t*32);
        float Bv[16], Cv[16];
        #pragma unroll
        for (int q = 0; q < 4; q++) {
            float4 v = p4[q];
            Bv[4*q+0] = v.x; Bv[4*q+1] = v.y; Bv[4*q+2] = v.z; Bv[4*q+3] = v.w;
        }
        #pragma unroll
        for (int q = 0; q < 4; q++) {
            float4 v = p4[4+q];
            Cv[4*q+0] = v.x; Cv[4*q+1] = v.y; Cv[4*q+2] = v.z; Cv[4*q+3] = v.w;
        }
        float dx = dlt * xv;
        float y = 0.f;
        #pragma unroll
        for (int s = 0; s < 16; s++) {
            float dA = __expf(dlt * Aa[s]);
            h[s] = fmaf(dA, h[s], dx * Bv[s]);
            y = fmaf(h[s], Cv[s], y);
        }
        g_y[tb + t*DI] = fmaf(Dd, xv, y);
    }
}

// -------- K6: gate by silu(z), GEMM (rows x 256) @ (256 x 128), add residual --------
__global__ void k_out(const float* __restrict__ W_out) {
    int row0 = blockIdx.x * 16, tid = threadIdx.x;   // 256 threads, 16 rows
    __shared__ float sh[16][256];
    for (int i = tid; i < 4096; i += 256) {
        int idx = row0*DI + i;
        sh[i>>8][i&255] = g_y[idx] * siluf(g_z[idx]);
    }
    __syncthreads();
    int j = tid & 127, g = tid >> 7;                 // 2 groups of 8 rows
    float acc[8];
    #pragma unroll
    for (int r = 0; r < 8; r++) acc[r] = 0.f;
    for (int k = 0; k < 256; k++) {
        float w = W_out[k*DM + j];
        #pragma unroll
        for (int r = 0; r < 8; r++) acc[r] = fmaf(sh[g*8 + r][k], w, acc[r]);
    }
    #pragma unroll
    for (int r = 0; r < 8; r++) {
        int row = row0 + g*8 + r;
        g_u[row*DM + j] = g_u[row*DM + j] + acc[r];
    }
}

// -------- K7: final RMSNorm then LayerNorm, per token row --------
__global__ void k_final(const float* __restrict__ rmsf_w, const float* __restrict__ ln_g,
                        const float* __restrict__ ln_b) {
    int row = blockIdx.x, k = threadIdx.x;           // 128 threads
    int w = k >> 5, lane = k & 31;
    __shared__ float s0[4], s1[4], s2[4];
    float v = g_u[row*DM + k];
    float ss = v*v;
    #pragma unroll
    for (int o = 16; o > 0; o >>= 1) ss += __shfl_xor_sync(0xffffffffu, ss, o);
    if (lane == 0) s0[w] = ss;
    __syncthreads();
    float tot = s0[0] + s0[1] + s0[2] + s0[3];
    float v1 = v * rsqrtf(tot * (1.f/128.f) + EPSF) * rmsf_w[k];
    float a = v1, b = v1*v1;
    #pragma unroll
    for (int o = 16; o > 0; o >>= 1) {
        a += __shfl_xor_sync(0xffffffffu, a, o);
        b += __shfl_xor_sync(0xffffffffu, b, o);
    }
    if (lane == 0) { s1[w] = a; s2[w] = b; }
    __syncthreads();
    float mu  = (s1[0]+s1[1]+s1[2]+s1[3]) * (1.f/128.f);
    float var = (s2[0]+s2[1]+s2[2]+s2[3]) * (1.f/128.f) - mu*mu;
    g_u[row*DM + k] = (v1 - mu) * rsqrtf(var + EPSF) * ln_g[k] + ln_b[k];
}

// -------- K8: head GEMM split-K: (32 x 32768) @ (32768 x 96), W read once --------
__global__ void k_head(const float* __restrict__ W_head) {
    int c = blockIdx.x, tid = threadIdx.x;           // 128 chunks of K=256, 384 threads
    __shared__ float sf[32][256];
    int c0 = c * 256;
    for (int i = tid; i < 8192; i += 384) {
        int bm = i >> 8, kk = i & 255;
        sf[bm][kk] = g_u[bm*KH + c0 + kk];
    }
    __syncthreads();
    int j = tid % 96, g = tid / 96;                  // g in 0..3 -> 8 seq rows each
    float acc[8];
    #pragma unroll
    for (int r = 0; r < 8; r++) acc[r] = 0.f;
    for (int kk = 0; kk < 256; kk++) {
        float w = W_head[(c0 + kk)*96 + j];
        #pragma unroll
        for (int r = 0; r < 8; r++) acc[r] = fmaf(sf[g*8 + r][kk], w, acc[r]);
    }
    #pragma unroll
    for (int r = 0; r < 8; r++)
        g_part[((size_t)c*32 + g*8 + r)*PLEN + j] = acc[r];
}

// -------- K9: reduce partials, de-normalize, write output --------
__global__ void k_reduce(const float* __restrict__ b_head, float* __restrict__ out) {
    int bm = blockIdx.x, j = threadIdx.x;            // 32 blocks x 96 threads
    float acc = b_head[j];
    for (int c = 0; c < 128; c++) acc += g_part[(c*32 + bm)*PLEN + j];
    out[bm*PLEN + j] = acc * g_std[bm] + g_mean[bm];
}

extern "C" void kernel_launch(void* const* d_in, const int* in_sizes, int n_in,
                              void* d_out, int out_size) {
    const float* x      = (const float*)d_in[0];
    const float* W_pe   = (const float*)d_in[1];
    const float* b_pe   = (const float*)d_in[2];
    const float* pos    = (const float*)d_in[3];
    const float* rms_w  = (const float*)d_in[4];
    const float* W_in   = (const float*)d_in[5];
    const float* conv_w = (const float*)d_in[6];
    const float* conv_b = (const float*)d_in[7];
    const float* W_xp   = (const float*)d_in[8];
    const float* W_dt   = (const float*)d_in[9];
    const float* b_dt   = (const float*)d_in[10];
    const float* A_log  = (const float*)d_in[11];
    const float* D_ssm  = (const float*)d_in[12];
    const float* W_out  = (const float*)d_in[13];
    const float* rmsf_w = (const float*)d_in[14];
    const float* ln_g   = (const float*)d_in[15];
    const float* ln_b   = (const float*)d_in[16];
    const float* W_head = (const float*)d_in[17];
    const float* b_head = (const float*)d_in[18];

    k_stats<<<BMSZ, 256>>>(x);
    k_embed<<<dim3(NP, BMSZ), DM>>>(x, W_pe, b_pe, pos);

    for (int l = 0; l < 2; l++) {
        k_in  <<<BMSZ*NP/16, 256>>>(rms_w + l*DM, W_in + l*DM*2*DI);
        k_conv<<<dim3(NP, BMSZ), DI>>>(conv_w + l*DI*4, conv_b + l*DI);
        k_dbc <<<BMSZ*NP/32, 256>>>(W_xp + l*DI*40, W_dt + l*DTR*DI, b_dt + l*DI);
        k_scan<<<BMSZ, DI>>>(A_log + l*DI*DS, D_ssm + l*DI);
        k_out <<<BMSZ*NP/16, 256>>>(W_out + l*DI*DM);
    }

    k_final<<<BMSZ*NP, DM>>>(rmsf_w, ln_g, ln_b);
    k_head<<<KH/256, 384>>>(W_head);
    k_reduce<<<BMSZ, PLEN>>>(b_head, (float*)d_out);
}

// round 3
// speedup vs baseline: 1.7352x; 1.7352x over previous
#include <cuda_runtime.h>
#include <math.h>

#define BMSZ 32
#define LSEQ 2048
#define NP   256
#define DM   128
#define DI   256
#define DS   16
#define DTR  8
#define PLEN 96
#define KH   (NP*DM)   /* 32768 */
#define EPSF 1e-5f

// -------- scratch (device globals; no allocation) --------
__device__ float g_mean[BMSZ];
__device__ float g_std[BMSZ];
__device__ float g_rstd[BMSZ];
__device__ float g_u[BMSZ*NP*DM];        // residual stream (4 MB)
__device__ float g_xb[BMSZ*NP*DI];       // 8 MB
__device__ float g_z[BMSZ*NP*DI];        // 8 MB
__device__ float g_xs[BMSZ*NP*DI];       // 8 MB
__device__ float g_delta[BMSZ*NP*DI];    // 8 MB
__device__ float g_bc[BMSZ*NP*32];       // B(16) then C(16) per token, 1 MB
__device__ float g_y[BMSZ*NP*DI];        // 8 MB
__device__ float g_part[128*BMSZ*PLEN];  // split-K head partials

__device__ __forceinline__ float siluf(float x) { return x / (1.f + __expf(-x)); }

// -------- K0: per-sequence mean/std over L --------
__global__ void k_stats(const float* __restrict__ x) {
    int bm = blockIdx.x, tid = threadIdx.x;
    float s = 0.f, s2 = 0.f;
    for (int i = tid; i < LSEQ; i += 256) {
        float v = x[bm*LSEQ + i];
        s += v; s2 += v*v;
    }
    __shared__ float sa[256], sb[256];
    sa[tid] = s; sb[tid] = s2; __syncthreads();
    for (int off = 128; off > 0; off >>= 1) {
        if (tid < off) { sa[tid] += sa[tid+off]; sb[tid] += sb[tid+off]; }
        __syncthreads();
    }
    if (tid == 0) {
        float m = sa[0] * (1.f/LSEQ);
        float var = sb[0] * (1.f/LSEQ) - m*m;
        float st = sqrtf(var + EPSF);
        g_mean[bm] = m; g_std[bm] = st; g_rstd[bm] = 1.f/st;
    }
}

// -------- K1: patch embedding: u = patches @ W_pe + b_pe + pos --------
__global__ void k_embed(const float* __restrict__ x, const float* __restrict__ W_pe,
                        const float* __restrict__ b_pe, const float* __restrict__ pos) {
    int p = blockIdx.x, bm = blockIdx.y, j = threadIdx.x;  // 128 threads
    __shared__ float sp[16];
    if (j < 16) {
        int t = p*8 + j; if (t > LSEQ-1) t = LSEQ-1;       // right-pad with last value
        sp[j] = (x[bm*LSEQ + t] - g_mean[bm]) * g_rstd[bm];
    }
    __syncthreads();
    float acc = b_pe[j] + pos[p*DM + j];
    #pragma unroll
    for (int k = 0; k < 16; k++) acc = fmaf(sp[k], W_pe[k*DM + j], acc);
    g_u[(bm*NP + p)*DM + j] = acc;
}

// -------- K2: RMSNorm + GEMM (32 rows x 128) @ (128 x 512) -> xb, z --------
__global__ void k_in(const float* __restrict__ rms_w, const float* __restrict__ W_in) {
    int row0 = blockIdx.x * 32, tid = threadIdx.x;   // 512 threads, 32 rows/block
    __shared__ float sh[32][128];
    __shared__ float ssc[32];
    for (int i = tid; i < 32*128; i += 512) sh[i>>7][i&127] = g_u[row0*DM + i];
    __syncthreads();
    int w = tid >> 5, lane = tid & 31;               // 16 warps x 2 rows each
    #pragma unroll
    for (int rr = 0; rr < 2; rr++) {
        int r = w*2 + rr;
        float ss = 0.f;
        #pragma unroll
        for (int q = 0; q < 4; q++) { float v = sh[r][lane + 32*q]; ss += v*v; }
        #pragma unroll
        for (int o = 16; o > 0; o >>= 1) ss += __shfl_xor_sync(0xffffffffu, ss, o);
        if (lane == 0) ssc[r] = rsqrtf(ss * (1.f/128.f) + EPSF);
    }
    __syncthreads();
    for (int i = tid; i < 32*128; i += 512) {
        int r = i>>7, k = i&127;
        sh[r][k] *= ssc[r] * rms_w[k];
    }
    __syncthreads();
    float acc[32];
    #pragma unroll
    for (int r = 0; r < 32; r++) acc[r] = 0.f;
    for (int k = 0; k < 128; k += 4) {
        float w0 = W_in[(k+0)*512 + tid];
        float w1 = W_in[(k+1)*512 + tid];
        float w2 = W_in[(k+2)*512 + tid];
        float w3 = W_in[(k+3)*512 + tid];
        #pragma unroll
        for (int r = 0; r < 32; r++) {
            float4 v = *reinterpret_cast<const float4*>(&sh[r][k]);
            float a = acc[r];
            a = fmaf(v.x, w0, a); a = fmaf(v.y, w1, a);
            a = fmaf(v.z, w2, a); a = fmaf(v.w, w3, a);
            acc[r] = a;
        }
    }
    if (tid < 256) {
        #pragma unroll
        for (int r = 0; r < 32; r++) g_xb[(row0+r)*DI + tid] = acc[r];
    } else {
        #pragma unroll
        for (int r = 0; r < 32; r++) g_z[(row0+r)*DI + tid - 256] = acc[r];
    }
}

// -------- K3: fused causal conv4+SiLU -> xs ; dbc = xs@W_xp ; delta = softplus(...) ; stash B,C --------
__global__ void k_cdbc(const float* __restrict__ conv_w, const float* __restrict__ conv_b,
                       const float* __restrict__ W_xp, const float* __restrict__ W_dt,
                       const float* __restrict__ b_dt) {
    int tok0 = blockIdx.x * 32, tid = threadIdx.x;   // 256 threads, 32 tokens/block
    __shared__ float sxs[32*257];                    // padded
    __shared__ float sdbc[32*40];
    // --- conv + silu: thread = channel, rolling window over 32 tokens ---
    float4 cw = reinterpret_cast<const float4*>(conv_w)[tid];
    float cb = conv_b[tid];
    const float* xb = g_xb + tok0*DI + tid;
    bool seqstart = (tok0 & (NP-1)) == 0;
    float x0, x1, x2;
    if (seqstart) { x0 = 0.f; x1 = 0.f; x2 = 0.f; }
    else { x0 = xb[-3*DI]; x1 = xb[-2*DI]; x2 = xb[-1*DI]; }
    #pragma unroll 4
    for (int t = 0; t < 32; t++) {
        float x3 = xb[t*DI];
        float a = cb;
        a = fmaf(cw.x, x0, a); a = fmaf(cw.y, x1, a);
        a = fmaf(cw.z, x2, a); a = fmaf(cw.w, x3, a);
        float v = siluf(a);
        sxs[t*257 + tid] = v;
        g_xs[(tok0+t)*DI + tid] = v;
        x0 = x1; x1 = x2; x2 = x3;
    }
    __syncthreads();
    // --- dbc GEMM (32 x 256)@(256 x 40) ---
    int o8 = tid & 7, tt = tid >> 3;                 // 32 tokens x 8 outputs -> 5 rounds
    for (int oo = 0; oo < 5; oo++) {
        int o = oo*8 + o8;
        float acc = 0.f;
        for (int k = 0; k < 256; k++) acc = fmaf(sxs[tt*257 + k], W_xp[k*40 + o], acc);
        sdbc[tt*40 + o] = acc;
    }
    __syncthreads();
    // --- delta ---
    float wdt[8];
    #pragma unroll
    for (int r = 0; r < 8; r++) wdt[r] = W_dt[r*DI + tid];
    float bd = b_dt[tid];
    for (int t2 = 0; t2 < 32; t2++) {
        float acc = bd;
        #pragma unroll
        for (int r = 0; r < 8; r++) acc = fmaf(sdbc[t2*40 + r], wdt[r], acc);
        float dl = (acc > 20.f) ? acc : log1pf(__expf(acc));
        g_delta[(tok0+t2)*DI + tid] = dl;
    }
    for (int i = tid; i < 1024; i += 256) {
        int t2 = i >> 5, v = i & 31;
        g_bc[(tok0+t2)*32 + v] = sdbc[t2*40 + 8 + v];
    }
}

// -------- K4: selective scan, state-parallel: thread = (channel, state) --------
__global__ void k_scan(const float* __restrict__ A_log, const float* __restrict__ D_ssm) {
    int dch = blockIdx.x, bm = blockIdx.y;           // grid (16, 32)
    int tid = threadIdx.x;                           // 256 = 16 d x 16 s
    int s = tid & 15, dl = tid >> 4;
    int d = dch*16 + dl;
    float Aa = -__expf(A_log[d*16 + s]);
    float Dd = D_ssm[d];
    float h = 0.f;
    int tb = bm*NP*DI + d;
    const float* __restrict__ bcb = g_bc + bm*NP*32;
    // prefetch t=0
    float dlt = __ldg(&g_delta[tb]), xv = __ldg(&g_xs[tb]);
    float Bv = __ldg(&bcb[s]), Cv = __ldg(&bcb[16 + s]);
    for (int t = 0; t < NP; t++) {
        int tn = (t+1 < NP) ? (t+1) : t;
        float n_dlt = __ldg(&g_delta[tb + tn*DI]);
        float n_xv  = __ldg(&g_xs  [tb + tn*DI]);
        float n_Bv  = __ldg(&bcb[tn*32 + s]);
        float n_Cv  = __ldg(&bcb[tn*32 + 16 + s]);
        float dA = __expf(dlt * Aa);
        h = fmaf(dA, h, dlt * xv * Bv);
        float p = h * Cv;
        p += __shfl_xor_sync(0xffffffffu, p, 8);
        p += __shfl_xor_sync(0xffffffffu, p, 4);
        p += __shfl_xor_sync(0xffffffffu, p, 2);
        p += __shfl_xor_sync(0xffffffffu, p, 1);
        if (s == 0) g_y[tb + t*DI] = fmaf(Dd, xv, p);
        dlt = n_dlt; xv = n_xv; Bv = n_Bv; Cv = n_Cv;
    }
}

// -------- K5: gate by silu(z), GEMM (32 rows x 256) @ (256 x 128), add residual --------
__global__ void k_out(const float* __restrict__ W_out) {
    int row0 = blockIdx.x * 32, tid = threadIdx.x;   // 256 threads, 32 rows
    __shared__ float sh[32][256];
    for (int i = tid; i < 32*256; i += 256) {
        int idx = row0*DI + i;
        sh[i>>8][i&255] = g_y[idx] * siluf(g_z[idx]);
    }
    __syncthreads();
    int j = tid & 127, g = tid >> 7;                 // 2 groups of 16 rows
    float acc[16];
    #pragma unroll
    for (int r = 0; r < 16; r++) acc[r] = 0.f;
    for (int k = 0; k < 256; k += 4) {
        float w0 = W_out[(k+0)*DM + j];
        float w1 = W_out[(k+1)*DM + j];
        float w2 = W_out[(k+2)*DM + j];
        float w3 = W_out[(k+3)*DM + j];
        #pragma unroll
        for (int r = 0; r < 16; r++) {
            float4 v = *reinterpret_cast<const float4*>(&sh[g*16 + r][k]);
            float a = acc[r];
            a = fmaf(v.x, w0, a); a = fmaf(v.y, w1, a);
            a = fmaf(v.z, w2, a); a = fmaf(v.w, w3, a);
            acc[r] = a;
        }
    }
    #pragma unroll
    for (int r = 0; r < 16; r++) {
        int row = row0 + g*16 + r;
        g_u[row*DM + j] = g_u[row*DM + j] + acc[r];
    }
}

// -------- K6: fused final RMSNorm+LayerNorm + head GEMM split-K chunk --------
__global__ void k_head(const float* __restrict__ rmsf_w, const float* __restrict__ ln_g,
                       const float* __restrict__ ln_b, const float* __restrict__ W_head) {
    int c = blockIdx.x, tid = threadIdx.x;           // 128 chunks of K=256, 384 threads
    __shared__ float sf[32][256];
    int c0 = c * 256;
    for (int i = tid; i < 32*256; i += 384) {
        int bm = i >> 8, kk = i & 255;
        sf[bm][kk] = g_u[bm*KH + c0 + kk];
    }
    __syncthreads();
    // normalize 64 segments of 128 (each = one (bm, patch) row), 12 warps
    int w = tid >> 5, lane = tid & 31;
    for (int seg = w; seg < 64; seg += 12) {
        int bm = seg >> 1, half = seg & 1;
        float* p = &sf[bm][half*128];
        float v[4];
        float ss = 0.f;
        #pragma unroll
        for (int q = 0; q < 4; q++) { v[q] = p[lane + 32*q]; ss += v[q]*v[q]; }
        #pragma unroll
        for (int o = 16; o > 0; o >>= 1) ss += __shfl_xor_sync(0xffffffffu, ss, o);
        float rs = rsqrtf(ss * (1.f/128.f) + EPSF);
        float a = 0.f, b = 0.f;
        #pragma unroll
        for (int q = 0; q < 4; q++) {
            v[q] = v[q] * rs * rmsf_w[lane + 32*q];
            a += v[q]; b += v[q]*v[q];
        }
        #pragma unroll
        for (int o = 16; o > 0; o >>= 1) {
            a += __shfl_xor_sync(0xffffffffu, a, o);
            b += __shfl_xor_sync(0xffffffffu, b, o);
        }
        float mu  = a * (1.f/128.f);
        float var = b * (1.f/128.f) - mu*mu;
        float rstd = rsqrtf(var + EPSF);
        #pragma unroll
        for (int q = 0; q < 4; q++) {
            int col = lane + 32*q;
            p[col] = (v[q] - mu) * rstd * ln_g[col] + ln_b[col];
        }
    }
    __syncthreads();
    // GEMM: (32 x 256)@(256 x 96) partial
    int j = tid % 96, g = tid / 96;                  // g in 0..3 -> 8 seq rows each
    float acc[8];
    #pragma unroll
    for (int r = 0; r < 8; r++) acc[r] = 0.f;
    for (int kk = 0; kk < 256; kk += 4) {
        float w0 = W_head[(c0+kk+0)*96 + j];
        float w1 = W_head[(c0+kk+1)*96 + j];
        float w2 = W_head[(c0+kk+2)*96 + j];
        float w3 = W_head[(c0+kk+3)*96 + j];
        #pragma unroll
        for (int r = 0; r < 8; r++) {
            float4 v = *reinterpret_cast<const float4*>(&sf[g*8 + r][kk]);
            float a = acc[r];
            a = fmaf(v.x, w0, a); a = fmaf(v.y, w1, a);
            a = fmaf(v.z, w2, a); a = fmaf(v.w, w3, a);
            acc[r] = a;
        }
    }
    #pragma unroll
    for (int r = 0; r < 8; r++)
        g_part[((size_t)c*32 + g*8 + r)*PLEN + j] = acc[r];
}

// -------- K7: reduce partials, de-normalize, write output --------
__global__ void k_reduce(const float* __restrict__ b_head, float* __restrict__ out) {
    int bm = blockIdx.x, j = threadIdx.x;            // 32 blocks x 96 threads
    float acc = b_head[j];
    for (int c = 0; c < 128; c++) acc += g_part[(c*32 + bm)*PLEN + j];
    out[bm*PLEN + j] = acc * g_std[bm] + g_mean[bm];
}

extern "C" void kernel_launch(void* const* d_in, const int* in_sizes, int n_in,
                              void* d_out, int out_size) {
    const float* x      = (const float*)d_in[0];
    const float* W_pe   = (const float*)d_in[1];
    const float* b_pe   = (const float*)d_in[2];
    const float* pos    = (const float*)d_in[3];
    const float* rms_w  = (const float*)d_in[4];
    const float* W_in   = (const float*)d_in[5];
    const float* conv_w = (const float*)d_in[6];
    const float* conv_b = (const float*)d_in[7];
    const float* W_xp   = (const float*)d_in[8];
    const float* W_dt   = (const float*)d_in[9];
    const float* b_dt   = (const float*)d_in[10];
    const float* A_log  = (const float*)d_in[11];
    const float* D_ssm  = (const float*)d_in[12];
    const float* W_out  = (const float*)d_in[13];
    const float* rmsf_w = (const float*)d_in[14];
    const float* ln_g   = (const float*)d_in[15];
    const float* ln_b   = (const float*)d_in[16];
    const float* W_head = (const float*)d_in[17];
    const float* b_head = (const float*)d_in[18];

    k_stats<<<BMSZ, 256>>>(x);
    k_embed<<<dim3(NP, BMSZ), DM>>>(x, W_pe, b_pe, pos);

    for (int l = 0; l < 2; l++) {
        k_in  <<<BMSZ*NP/32, 512>>>(rms_w + l*DM, W_in + l*DM*2*DI);
        k_cdbc<<<BMSZ*NP/32, 256>>>(conv_w + l*DI*4, conv_b + l*DI,
                                    W_xp + l*DI*40, W_dt + l*DTR*DI, b_dt + l*DI);
        k_scan<<<dim3(16, BMSZ), 256>>>(A_log + l*DI*DS, D_ssm + l*DI);
        k_out <<<BMSZ*NP/32, 256>>>(W_out + l*DI*DM);
    }

    k_head<<<KH/256, 384>>>(rmsf_w, ln_g, ln_b, W_head);
    k_reduce<<<BMSZ, PLEN>>>(b_head, (float*)d_out);
}

// round 4
// speedup vs baseline: 1.9136x; 1.1028x over previous
#include <cuda_runtime.h>
#include <math.h>

#define BMSZ 32
#define LSEQ 2048
#define NP   256
#define DM   128
#define DI   256
#define DS   16
#define DTR  8
#define PLEN 96
#define KH   (NP*DM)   /* 32768 */
#define EPSF 1e-5f

// -------- scratch (device globals; no allocation) --------
__device__ float g_mean[BMSZ];
__device__ float g_std[BMSZ];
__device__ float g_rstd[BMSZ];
__device__ float g_u[BMSZ*NP*DM];        // residual stream (4 MB)
__device__ float g_xb[BMSZ*NP*DI];       // 8 MB
__device__ float g_z[BMSZ*NP*DI];        // 8 MB
__device__ float g_xs[BMSZ*NP*DI];       // 8 MB
__device__ float g_delta[BMSZ*NP*DI];    // 8 MB
__device__ float g_bc[BMSZ*NP*32];       // B(16) then C(16) per token, 1 MB
__device__ float g_y[BMSZ*NP*DI];        // 8 MB
__device__ float g_part[256*BMSZ*PLEN];  // split-K head partials

__device__ __forceinline__ float siluf(float x) { return x / (1.f + __expf(-x)); }

// -------- K0: per-sequence mean/std over L --------
__global__ void k_stats(const float* __restrict__ x) {
    int bm = blockIdx.x, tid = threadIdx.x;
    float s = 0.f, s2 = 0.f;
    for (int i = tid; i < LSEQ; i += 256) {
        float v = x[bm*LSEQ + i];
        s += v; s2 += v*v;
    }
    __shared__ float sa[256], sb[256];
    sa[tid] = s; sb[tid] = s2; __syncthreads();
    for (int off = 128; off > 0; off >>= 1) {
        if (tid < off) { sa[tid] += sa[tid+off]; sb[tid] += sb[tid+off]; }
        __syncthreads();
    }
    if (tid == 0) {
        float m = sa[0] * (1.f/LSEQ);
        float var = sb[0] * (1.f/LSEQ) - m*m;
        float st = sqrtf(var + EPSF);
        g_mean[bm] = m; g_std[bm] = st; g_rstd[bm] = 1.f/st;
    }
}

// -------- K1: patch embedding: u = patches @ W_pe + b_pe + pos --------
__global__ void k_embed(const float* __restrict__ x, const float* __restrict__ W_pe,
                        const float* __restrict__ b_pe, const float* __restrict__ pos) {
    int p = blockIdx.x, bm = blockIdx.y, j = threadIdx.x;  // 128 threads
    __shared__ float sp[16];
    if (j < 16) {
        int t = p*8 + j; if (t > LSEQ-1) t = LSEQ-1;       // right-pad with last value
        sp[j] = (x[bm*LSEQ + t] - g_mean[bm]) * g_rstd[bm];
    }
    __syncthreads();
    float acc = b_pe[j] + pos[p*DM + j];
    #pragma unroll
    for (int k = 0; k < 16; k++) acc = fmaf(sp[k], W_pe[k*DM + j], acc);
    g_u[(bm*NP + p)*DM + j] = acc;
}

// -------- K2: RMSNorm + GEMM (32 rows x 128) @ (128 x 512) -> xb, z --------
__global__ void k_in(const float* __restrict__ rms_w, const float* __restrict__ W_in) {
    int row0 = blockIdx.x * 32, tid = threadIdx.x;   // 512 threads, 32 rows/block
    __shared__ float sh[32][128];
    __shared__ float ssc[32];
    for (int i = tid; i < 32*128; i += 512) sh[i>>7][i&127] = g_u[row0*DM + i];
    __syncthreads();
    int w = tid >> 5, lane = tid & 31;               // 16 warps x 2 rows each
    #pragma unroll
    for (int rr = 0; rr < 2; rr++) {
        int r = w*2 + rr;
        float ss = 0.f;
        #pragma unroll
        for (int q = 0; q < 4; q++) { float v = sh[r][lane + 32*q]; ss += v*v; }
        #pragma unroll
        for (int o = 16; o > 0; o >>= 1) ss += __shfl_xor_sync(0xffffffffu, ss, o);
        if (lane == 0) ssc[r] = rsqrtf(ss * (1.f/128.f) + EPSF);
    }
    __syncthreads();
    for (int i = tid; i < 32*128; i += 512) {
        int r = i>>7, k = i&127;
        sh[r][k] *= ssc[r] * rms_w[k];
    }
    __syncthreads();
    float acc[32];
    #pragma unroll
    for (int r = 0; r < 32; r++) acc[r] = 0.f;
    for (int k = 0; k < 128; k += 4) {
        float w0 = W_in[(k+0)*512 + tid];
        float w1 = W_in[(k+1)*512 + tid];
        float w2 = W_in[(k+2)*512 + tid];
        float w3 = W_in[(k+3)*512 + tid];
        #pragma unroll
        for (int r = 0; r < 32; r++) {
            float4 v = *reinterpret_cast<const float4*>(&sh[r][k]);
            float a = acc[r];
            a = fmaf(v.x, w0, a); a = fmaf(v.y, w1, a);
            a = fmaf(v.z, w2, a); a = fmaf(v.w, w3, a);
            acc[r] = a;
        }
    }
    if (tid < 256) {
        #pragma unroll
        for (int r = 0; r < 32; r++) g_xb[(row0+r)*DI + tid] = acc[r];
    } else {
        #pragma unroll
        for (int r = 0; r < 32; r++) g_z[(row0+r)*DI + tid - 256] = acc[r];
    }
}

// -------- K3: fused conv4+SiLU ; dbc GEMM ; delta ; B,C stash. 16 tokens/block --------
__global__ void k_cdbc(const float* __restrict__ conv_w, const float* __restrict__ conv_b,
                       const float* __restrict__ W_xp, const float* __restrict__ W_dt,
                       const float* __restrict__ b_dt) {
    int tok0 = blockIdx.x * 16, tid = threadIdx.x;   // 512 blocks, 256 threads
    __shared__ float sxs[16*257];                    // [t][k], pad 257
    __shared__ float sdbc[16*40];
    // --- conv + silu: thread = channel, rolling window over 16 tokens ---
    float4 cw = reinterpret_cast<const float4*>(conv_w)[tid];
    float cb = conv_b[tid];
    const float* xb = g_xb + tok0*DI + tid;
    bool seqstart = (tok0 & (NP-1)) == 0;
    float x0, x1, x2;
    if (seqstart) { x0 = 0.f; x1 = 0.f; x2 = 0.f; }
    else { x0 = xb[-3*DI]; x1 = xb[-2*DI]; x2 = xb[-1*DI]; }
    #pragma unroll 4
    for (int t = 0; t < 16; t++) {
        float x3 = xb[t*DI];
        float a = cb;
        a = fmaf(cw.x, x0, a); a = fmaf(cw.y, x1, a);
        a = fmaf(cw.z, x2, a); a = fmaf(cw.w, x3, a);
        float v = siluf(a);
        sxs[t*257 + tid] = v;
        g_xs[(tok0+t)*DI + tid] = v;
        x0 = x1; x1 = x2; x2 = x3;
    }
    __syncthreads();
    // --- dbc GEMM: 16 tokens x 16 threads/token; 3 accumulators each ---
    {
        int tt = tid >> 4, o = tid & 15;             // outputs o, o+16, (o+32 if o<8)
        const float* sr = &sxs[tt*257];
        float a0 = 0.f, a1 = 0.f, a2 = 0.f;
        #pragma unroll 4
        for (int k = 0; k < 256; k++) {
            float v = sr[k];
            float w0 = __ldg(&W_xp[k*40 + o]);
            float w1 = __ldg(&W_xp[k*40 + o + 16]);
            a0 = fmaf(v, w0, a0);
            a1 = fmaf(v, w1, a1);
            if (o < 8) {
                float w2 = __ldg(&W_xp[k*40 + o + 32]);
                a2 = fmaf(v, w2, a2);
            }
        }
        sdbc[tt*40 + o]      = a0;
        sdbc[tt*40 + o + 16] = a1;
        if (o < 8) sdbc[tt*40 + o + 32] = a2;
    }
    __syncthreads();
    // --- delta: thread = channel, 16 tokens ---
    float wdt[8];
    #pragma unroll
    for (int r = 0; r < 8; r++) wdt[r] = W_dt[r*DI + tid];
    float bd = b_dt[tid];
    #pragma unroll 2
    for (int t2 = 0; t2 < 16; t2++) {
        float acc = bd;
        #pragma unroll
        for (int r = 0; r < 8; r++) acc = fmaf(sdbc[t2*40 + r], wdt[r], acc);
        float dl = (acc > 20.f) ? acc : log1pf(__expf(acc));
        g_delta[(tok0+t2)*DI + tid] = dl;
    }
    // --- stash B,C: 16 tokens x 32 values ---
    for (int i = tid; i < 512; i += 256) {
        int t2 = i >> 5, v = i & 31;
        g_bc[(tok0+t2)*32 + v] = sdbc[t2*40 + 8 + v];
    }
}

// -------- K4: selective scan, state-parallel: thread = (channel, state) --------
__global__ void k_scan(const float* __restrict__ A_log, const float* __restrict__ D_ssm) {
    int dch = blockIdx.x, bm = blockIdx.y;           // grid (16, 32)
    int tid = threadIdx.x;                           // 256 = 16 d x 16 s
    int s = tid & 15, dl = tid >> 4;
    int d = dch*16 + dl;
    float Aa = -__expf(A_log[d*16 + s]);
    float Dd = D_ssm[d];
    float h = 0.f;
    int tb = bm*NP*DI + d;
    const float* __restrict__ bcb = g_bc + bm*NP*32;
    float dlt = __ldg(&g_delta[tb]), xv = __ldg(&g_xs[tb]);
    float Bv = __ldg(&bcb[s]), Cv = __ldg(&bcb[16 + s]);
    for (int t = 0; t < NP; t++) {
        int tn = (t+1 < NP) ? (t+1) : t;
        float n_dlt = __ldg(&g_delta[tb + tn*DI]);
        float n_xv  = __ldg(&g_xs  [tb + tn*DI]);
        float n_Bv  = __ldg(&bcb[tn*32 + s]);
        float n_Cv  = __ldg(&bcb[tn*32 + 16 + s]);
        float dA = __expf(dlt * Aa);
        h = fmaf(dA, h, dlt * xv * Bv);
        float p = h * Cv;
        p += __shfl_xor_sync(0xffffffffu, p, 8);
        p += __shfl_xor_sync(0xffffffffu, p, 4);
        p += __shfl_xor_sync(0xffffffffu, p, 2);
        p += __shfl_xor_sync(0xffffffffu, p, 1);
        if (s == 0) g_y[tb + t*DI] = fmaf(Dd, xv, p);
        dlt = n_dlt; xv = n_xv; Bv = n_Bv; Cv = n_Cv;
    }
}

// -------- K5: gate by silu(z), GEMM (32 rows x 256) @ (256 x 128), add residual --------
__global__ void k_out(const float* __restrict__ W_out) {
    int row0 = blockIdx.x * 32, tid = threadIdx.x;   // 512 threads, 32 rows
    __shared__ float sh[32][256];
    for (int i = tid; i < 32*256; i += 512) {
        int idx = row0*DI + i;
        sh[i>>8][i&255] = g_y[idx] * siluf(g_z[idx]);
    }
    __syncthreads();
    int j = tid & 127, g = tid >> 7;                 // 4 groups of 8 rows
    float acc[8];
    #pragma unroll
    for (int r = 0; r < 8; r++) acc[r] = 0.f;
    for (int k = 0; k < 256; k += 4) {
        float w0 = W_out[(k+0)*DM + j];
        float w1 = W_out[(k+1)*DM + j];
        float w2 = W_out[(k+2)*DM + j];
        float w3 = W_out[(k+3)*DM + j];
        #pragma unroll
        for (int r = 0; r < 8; r++) {
            float4 v = *reinterpret_cast<const float4*>(&sh[g*8 + r][k]);
            float a = acc[r];
            a = fmaf(v.x, w0, a); a = fmaf(v.y, w1, a);
            a = fmaf(v.z, w2, a); a = fmaf(v.w, w3, a);
            acc[r] = a;
        }
    }
    #pragma unroll
    for (int r = 0; r < 8; r++) {
        int row = row0 + g*8 + r;
        g_u[row*DM + j] = g_u[row*DM + j] + acc[r];
    }
}

// -------- K6: fused final RMSNorm+LayerNorm + head GEMM split-K chunk of 128 --------
__global__ void k_head(const float* __restrict__ rmsf_w, const float* __restrict__ ln_g,
                       const float* __restrict__ ln_b, const float* __restrict__ W_head) {
    int c = blockIdx.x, tid = threadIdx.x;           // 256 chunks of K=128, 384 threads
    __shared__ float sf[32][128];
    int c0 = c * 128;
    for (int i = tid; i < 32*128; i += 384) {
        int bm = i >> 7, kk = i & 127;
        sf[bm][kk] = g_u[bm*KH + c0 + kk];
    }
    __syncthreads();
    // each chunk row is exactly one (bm, patch) norm segment of 128
    int w = tid >> 5, lane = tid & 31;
    for (int bm = w; bm < 32; bm += 12) {
        float* p = &sf[bm][0];
        float v[4];
        float ss = 0.f;
        #pragma unroll
        for (int q = 0; q < 4; q++) { v[q] = p[lane + 32*q]; ss += v[q]*v[q]; }
        #pragma unroll
        for (int o = 16; o > 0; o >>= 1) ss += __shfl_xor_sync(0xffffffffu, ss, o);
        float rs = rsqrtf(ss * (1.f/128.f) + EPSF);
        float a = 0.f, b = 0.f;
        #pragma unroll
        for (int q = 0; q < 4; q++) {
            v[q] = v[q] * rs * rmsf_w[lane + 32*q];
            a += v[q]; b += v[q]*v[q];
        }
        #pragma unroll
        for (int o = 16; o > 0; o >>= 1) {
            a += __shfl_xor_sync(0xffffffffu, a, o);
            b += __shfl_xor_sync(0xffffffffu, b, o);
        }
        float mu  = a * (1.f/128.f);
        float var = b * (1.f/128.f) - mu*mu;
        float rstd = rsqrtf(var + EPSF);
        #pragma unroll
        for (int q = 0; q < 4; q++) {
            int col = lane + 32*q;
            p[col] = (v[q] - mu) * rstd * ln_g[col] + ln_b[col];
        }
    }
    __syncthreads();
    // GEMM: (32 x 128)@(128 x 96) partial
    int j = tid % 96, g = tid / 96;                  // g in 0..3 -> 8 seq rows each
    float acc[8];
    #pragma unroll
    for (int r = 0; r < 8; r++) acc[r] = 0.f;
    for (int kk = 0; kk < 128; kk += 4) {
        float w0 = W_head[(c0+kk+0)*96 + j];
        float w1 = W_head[(c0+kk+1)*96 + j];
        float w2 = W_head[(c0+kk+2)*96 + j];
        float w3 = W_head[(c0+kk+3)*96 + j];
        #pragma unroll
        for (int r = 0; r < 8; r++) {
            float4 v = *reinterpret_cast<const float4*>(&sf[g*8 + r][kk]);
            float a = acc[r];
            a = fmaf(v.x, w0, a); a = fmaf(v.y, w1, a);
            a = fmaf(v.z, w2, a); a = fmaf(v.w, w3, a);
            acc[r] = a;
        }
    }
    #pragma unroll
    for (int r = 0; r < 8; r++)
        g_part[((size_t)c*32 + g*8 + r)*PLEN + j] = acc[r];
}

// -------- K7: reduce partials, de-normalize, write output --------
__global__ void k_reduce(const float* __restrict__ b_head, float* __restrict__ out) {
    int bm = blockIdx.x, j = threadIdx.x;            // 32 blocks x 96 threads
    float acc = b_head[j];
    #pragma unroll 4
    for (int c = 0; c < 256; c++) acc += g_part[(c*32 + bm)*PLEN + j];
    out[bm*PLEN + j] = acc * g_std[bm] + g_mean[bm];
}

extern "C" void kernel_launch(void* const* d_in, const int* in_sizes, int n_in,
                              void* d_out, int out_size) {
    const float* x      = (const float*)d_in[0];
    const float* W_pe   = (const float*)d_in[1];
    const float* b_pe   = (const float*)d_in[2];
    const float* pos    = (const float*)d_in[3];
    const float* rms_w  = (const float*)d_in[4];
    const float* W_in   = (const float*)d_in[5];
    const float* conv_w = (const float*)d_in[6];
    const float* conv_b = (const float*)d_in[7];
    const float* W_xp   = (const float*)d_in[8];
    const float* W_dt   = (const float*)d_in[9];
    const float* b_dt   = (const float*)d_in[10];
    const float* A_log  = (const float*)d_in[11];
    const float* D_ssm  = (const float*)d_in[12];
    const float* W_out  = (const float*)d_in[13];
    const float* rmsf_w = (const float*)d_in[14];
    const float* ln_g   = (const float*)d_in[15];
    const float* ln_b   = (const float*)d_in[16];
    const float* W_head = (const float*)d_in[17];
    const float* b_head = (const float*)d_in[18];

    k_stats<<<BMSZ, 256>>>(x);
    k_embed<<<dim3(NP, BMSZ), DM>>>(x, W_pe, b_pe, pos);

    for (int l = 0; l < 2; l++) {
        k_in  <<<BMSZ*NP/32, 512>>>(rms_w + l*DM, W_in + l*DM*2*DI);
        k_cdbc<<<BMSZ*NP/16, 256>>>(conv_w + l*DI*4, conv_b + l*DI,
                                    W_xp + l*DI*40, W_dt + l*DTR*DI, b_dt + l*DI);
        k_scan<<<dim3(16, BMSZ), 256>>>(A_log + l*DI*DS, D_ssm + l*DI);
        k_out <<<BMSZ*NP/32, 512>>>(W_out + l*DI*DM);
    }

    k_head<<<KH/128, 384>>>(rmsf_w, ln_g, ln_b, W_head);
    k_reduce<<<BMSZ, PLEN>>>(b_head, (float*)d_out);
}

// round 5
// speedup vs baseline: 1.9440x; 1.0159x over previous
#include <cuda_runtime.h>
#include <math.h>

#define BMSZ 32
#define LSEQ 2048
#define NP   256
#define DM   128
#define DI   256
#define DS   16
#define DTR  8
#define PLEN 96
#define KH   (NP*DM)   /* 32768 */
#define EPSF 1e-5f

// -------- scratch (device globals; no allocation) --------
__device__ float g_mean[BMSZ];
__device__ float g_std[BMSZ];
__device__ float g_rstd[BMSZ];
__device__ float g_u[BMSZ*NP*DM];        // residual stream (4 MB)
__device__ float g_xb[BMSZ*NP*DI];       // 8 MB
__device__ float g_z[BMSZ*NP*DI];        // 8 MB
__device__ float g_xs[BMSZ*NP*DI];       // 8 MB
__device__ float g_delta[BMSZ*NP*DI];    // 8 MB
__device__ float g_bc[BMSZ*NP*32];       // B(16) then C(16) per token, 1 MB
__device__ float g_y[BMSZ*NP*DI];        // 8 MB
__device__ float g_part[256*BMSZ*PLEN];  // split-K head partials

__device__ __forceinline__ float siluf(float x) { return x / (1.f + __expf(-x)); }

// -------- K0: per-sequence mean/std over L --------
__global__ void k_stats(const float* __restrict__ x) {
    int bm = blockIdx.x, tid = threadIdx.x;
    float s = 0.f, s2 = 0.f;
    for (int i = tid; i < LSEQ; i += 256) {
        float v = x[bm*LSEQ + i];
        s += v; s2 += v*v;
    }
    __shared__ float sa[256], sb[256];
    sa[tid] = s; sb[tid] = s2; __syncthreads();
    for (int off = 128; off > 0; off >>= 1) {
        if (tid < off) { sa[tid] += sa[tid+off]; sb[tid] += sb[tid+off]; }
        __syncthreads();
    }
    if (tid == 0) {
        float m = sa[0] * (1.f/LSEQ);
        float var = sb[0] * (1.f/LSEQ) - m*m;
        float st = sqrtf(var + EPSF);
        g_mean[bm] = m; g_std[bm] = st; g_rstd[bm] = 1.f/st;
    }
}

// -------- K1: patch embedding: u = patches @ W_pe + b_pe + pos --------
__global__ void k_embed(const float* __restrict__ x, const float* __restrict__ W_pe,
                        const float* __restrict__ b_pe, const float* __restrict__ pos) {
    int p = blockIdx.x, bm = blockIdx.y, j = threadIdx.x;  // 128 threads
    __shared__ float sp[16];
    if (j < 16) {
        int t = p*8 + j; if (t > LSEQ-1) t = LSEQ-1;       // right-pad with last value
        sp[j] = (x[bm*LSEQ + t] - g_mean[bm]) * g_rstd[bm];
    }
    __syncthreads();
    float acc = b_pe[j] + pos[p*DM + j];
    #pragma unroll
    for (int k = 0; k < 16; k++) acc = fmaf(sp[k], W_pe[k*DM + j], acc);
    g_u[(bm*NP + p)*DM + j] = acc;
}

// -------- K2: RMSNorm + GEMM (32 rows x 128) @ (128 x 512) -> xb, z --------
__global__ void k_in(const float* __restrict__ rms_w, const float* __restrict__ W_in) {
    int row0 = blockIdx.x * 32, tid = threadIdx.x;   // 512 threads, 32 rows/block
    __shared__ float sh[32][128];
    __shared__ float ssc[32];
    for (int i = tid; i < 32*128; i += 512) sh[i>>7][i&127] = g_u[row0*DM + i];
    __syncthreads();
    int w = tid >> 5, lane = tid & 31;               // 16 warps x 2 rows each
    #pragma unroll
    for (int rr = 0; rr < 2; rr++) {
        int r = w*2 + rr;
        float ss = 0.f;
        #pragma unroll
        for (int q = 0; q < 4; q++) { float v = sh[r][lane + 32*q]; ss += v*v; }
        #pragma unroll
        for (int o = 16; o > 0; o >>= 1) ss += __shfl_xor_sync(0xffffffffu, ss, o);
        if (lane == 0) ssc[r] = rsqrtf(ss * (1.f/128.f) + EPSF);
    }
    __syncthreads();
    for (int i = tid; i < 32*128; i += 512) {
        int r = i>>7, k = i&127;
        sh[r][k] *= ssc[r] * rms_w[k];
    }
    __syncthreads();
    float acc[32];
    #pragma unroll
    for (int r = 0; r < 32; r++) acc[r] = 0.f;
    for (int k = 0; k < 128; k += 4) {
        float w0 = W_in[(k+0)*512 + tid];
        float w1 = W_in[(k+1)*512 + tid];
        float w2 = W_in[(k+2)*512 + tid];
        float w3 = W_in[(k+3)*512 + tid];
        #pragma unroll
        for (int r = 0; r < 32; r++) {
            float4 v = *reinterpret_cast<const float4*>(&sh[r][k]);
            float a = acc[r];
            a = fmaf(v.x, w0, a); a = fmaf(v.y, w1, a);
            a = fmaf(v.z, w2, a); a = fmaf(v.w, w3, a);
            acc[r] = a;
        }
    }
    if (tid < 256) {
        #pragma unroll
        for (int r = 0; r < 32; r++) g_xb[(row0+r)*DI + tid] = acc[r];
    } else {
        #pragma unroll
        for (int r = 0; r < 32; r++) g_z[(row0+r)*DI + tid - 256] = acc[r];
    }
}

// -------- K3: fused conv4+SiLU ; dbc GEMM (float4 weights) ; delta ; B,C stash --------
__global__ void k_cdbc(const float* __restrict__ conv_w, const float* __restrict__ conv_b,
                       const float* __restrict__ W_xp, const float* __restrict__ W_dt,
                       const float* __restrict__ b_dt) {
    int tok0 = blockIdx.x * 16, tid = threadIdx.x;   // 512 blocks, 256 threads
    __shared__ float sxs[16*257];                    // [t][k], pad 257
    __shared__ float sdbc[16*40];
    // --- conv + silu: thread = channel, rolling window over 16 tokens ---
    float4 cw = reinterpret_cast<const float4*>(conv_w)[tid];
    float cb = conv_b[tid];
    const float* xb = g_xb + tok0*DI + tid;
    bool seqstart = (tok0 & (NP-1)) == 0;
    float x0, x1, x2;
    if (seqstart) { x0 = 0.f; x1 = 0.f; x2 = 0.f; }
    else { x0 = xb[-3*DI]; x1 = xb[-2*DI]; x2 = xb[-1*DI]; }
    #pragma unroll 4
    for (int t = 0; t < 16; t++) {
        float x3 = xb[t*DI];
        float a = cb;
        a = fmaf(cw.x, x0, a); a = fmaf(cw.y, x1, a);
        a = fmaf(cw.z, x2, a); a = fmaf(cw.w, x3, a);
        float v = siluf(a);
        sxs[t*257 + tid] = v;
        g_xs[(tok0+t)*DI + tid] = v;
        x0 = x1; x1 = x2; x2 = x3;
    }
    __syncthreads();
    // --- dbc GEMM: 160 threads = 16 tokens x 10 output-quads; float4 weight loads ---
    if (tid < 160) {
        int tt = tid / 10, q = tid % 10;
        const float* sr = &sxs[tt*257];
        const float4* __restrict__ wq = reinterpret_cast<const float4*>(W_xp) + q;
        float4 a; a.x = 0.f; a.y = 0.f; a.z = 0.f; a.w = 0.f;
        #pragma unroll 8
        for (int k = 0; k < 256; k++) {
            float v = sr[k];
            float4 w4 = __ldg(&wq[k*10]);            // W_xp[k*40 + 4q .. +3]
            a.x = fmaf(v, w4.x, a.x); a.y = fmaf(v, w4.y, a.y);
            a.z = fmaf(v, w4.z, a.z); a.w = fmaf(v, w4.w, a.w);
        }
        *reinterpret_cast<float4*>(&sdbc[tt*40 + q*4]) = a;
    }
    __syncthreads();
    // --- delta: thread = channel, 16 tokens ---
    float wdt[8];
    #pragma unroll
    for (int r = 0; r < 8; r++) wdt[r] = W_dt[r*DI + tid];
    float bd = b_dt[tid];
    #pragma unroll 2
    for (int t2 = 0; t2 < 16; t2++) {
        float acc = bd;
        #pragma unroll
        for (int r = 0; r < 8; r++) acc = fmaf(sdbc[t2*40 + r], wdt[r], acc);
        float dl = (acc > 20.f) ? acc : log1pf(__expf(acc));
        g_delta[(tok0+t2)*DI + tid] = dl;
    }
    // --- stash B,C: 16 tokens x 32 values ---
    for (int i = tid; i < 512; i += 256) {
        int t2 = i >> 5, v = i & 31;
        g_bc[(tok0+t2)*32 + v] = sdbc[t2*40 + 8 + v];
    }
}

// -------- K4: selective scan, state-parallel: thread = (channel, state) --------
__global__ void k_scan(const float* __restrict__ A_log, const float* __restrict__ D_ssm) {
    int dch = blockIdx.x, bm = blockIdx.y;           // grid (16, 32)
    int tid = threadIdx.x;                           // 256 = 16 d x 16 s
    int s = tid & 15, dl = tid >> 4;
    int d = dch*16 + dl;
    float Aa = -__expf(A_log[d*16 + s]);
    float Dd = D_ssm[d];
    float h = 0.f;
    int tb = bm*NP*DI + d;
    const float* __restrict__ bcb = g_bc + bm*NP*32;
    float dlt = __ldg(&g_delta[tb]), xv = __ldg(&g_xs[tb]);
    float Bv = __ldg(&bcb[s]), Cv = __ldg(&bcb[16 + s]);
    for (int t = 0; t < NP; t++) {
        int tn = (t+1 < NP) ? (t+1) : t;
        float n_dlt = __ldg(&g_delta[tb + tn*DI]);
        float n_xv  = __ldg(&g_xs  [tb + tn*DI]);
        float n_Bv  = __ldg(&bcb[tn*32 + s]);
        float n_Cv  = __ldg(&bcb[tn*32 + 16 + s]);
        float dA = __expf(dlt * Aa);
        h = fmaf(dA, h, dlt * xv * Bv);
        float p = h * Cv;
        p += __shfl_xor_sync(0xffffffffu, p, 8);
        p += __shfl_xor_sync(0xffffffffu, p, 4);
        p += __shfl_xor_sync(0xffffffffu, p, 2);
        p += __shfl_xor_sync(0xffffffffu, p, 1);
        if (s == 0) g_y[tb + t*DI] = fmaf(Dd, xv, p);
        dlt = n_dlt; xv = n_xv; Bv = n_Bv; Cv = n_Cv;
    }
}

// -------- K5: gate by silu(z), GEMM (32 rows x 256) @ (256 x 128), add residual --------
__global__ void k_out(const float* __restrict__ W_out) {
    int row0 = blockIdx.x * 32, tid = threadIdx.x;   // 512 threads, 32 rows
    __shared__ float sh[32][256];
    for (int i = tid; i < 32*256; i += 512) {
        int idx = row0*DI + i;
        sh[i>>8][i&255] = g_y[idx] * siluf(g_z[idx]);
    }
    __syncthreads();
    int j = tid & 127, g = tid >> 7;                 // 4 groups of 8 rows
    float acc[8];
    #pragma unroll
    for (int r = 0; r < 8; r++) acc[r] = 0.f;
    for (int k = 0; k < 256; k += 4) {
        float w0 = W_out[(k+0)*DM + j];
        float w1 = W_out[(k+1)*DM + j];
        float w2 = W_out[(k+2)*DM + j];
        float w3 = W_out[(k+3)*DM + j];
        #pragma unroll
        for (int r = 0; r < 8; r++) {
            float4 v = *reinterpret_cast<const float4*>(&sh[g*8 + r][k]);
            float a = acc[r];
            a = fmaf(v.x, w0, a); a = fmaf(v.y, w1, a);
            a = fmaf(v.z, w2, a); a = fmaf(v.w, w3, a);
            acc[r] = a;
        }
    }
    #pragma unroll
    for (int r = 0; r < 8; r++) {
        int row = row0 + g*8 + r;
        g_u[row*DM + j] = g_u[row*DM + j] + acc[r];
    }
}

// -------- K6: fused final RMSNorm+LayerNorm + head GEMM split-K chunk of 128 --------
__global__ void k_head(const float* __restrict__ rmsf_w, const float* __restrict__ ln_g,
                       const float* __restrict__ ln_b, const float* __restrict__ W_head) {
    int c = blockIdx.x, tid = threadIdx.x;           // 256 chunks of K=128, 384 threads
    __shared__ float sf[32][128];
    int c0 = c * 128;
    for (int i = tid; i < 32*128; i += 384) {
        int bm = i >> 7, kk = i & 127;
        sf[bm][kk] = g_u[bm*KH + c0 + kk];
    }
    __syncthreads();
    // each chunk row is exactly one (bm, patch) norm segment of 128
    int w = tid >> 5, lane = tid & 31;
    for (int bm = w; bm < 32; bm += 12) {
        float* p = &sf[bm][0];
        float v[4];
        float ss = 0.f;
        #pragma unroll
        for (int q = 0; q < 4; q++) { v[q] = p[lane + 32*q]; ss += v[q]*v[q]; }
        #pragma unroll
        for (int o = 16; o > 0; o >>= 1) ss += __shfl_xor_sync(0xffffffffu, ss, o);
        float rs = rsqrtf(ss * (1.f/128.f) + EPSF);
        float a = 0.f, b = 0.f;
        #pragma unroll
        for (int q = 0; q < 4; q++) {
            v[q] = v[q] * rs * rmsf_w[lane + 32*q];
            a += v[q]; b += v[q]*v[q];
        }
        #pragma unroll
        for (int o = 16; o > 0; o >>= 1) {
            a += __shfl_xor_sync(0xffffffffu, a, o);
            b += __shfl_xor_sync(0xffffffffu, b, o);
        }
        float mu  = a * (1.f/128.f);
        float var = b * (1.f/128.f) - mu*mu;
        float rstd = rsqrtf(var + EPSF);
        #pragma unroll
        for (int q = 0; q < 4; q++) {
            int col = lane + 32*q;
            p[col] = (v[q] - mu) * rstd * ln_g[col] + ln_b[col];
        }
    }
    __syncthreads();
    // GEMM: (32 x 128)@(128 x 96) partial
    int j = tid % 96, g = tid / 96;                  // g in 0..3 -> 8 seq rows each
    float acc[8];
    #pragma unroll
    for (int r = 0; r < 8; r++) acc[r] = 0.f;
    for (int kk = 0; kk < 128; kk += 4) {
        float w0 = W_head[(c0+kk+0)*96 + j];
        float w1 = W_head[(c0+kk+1)*96 + j];
        float w2 = W_head[(c0+kk+2)*96 + j];
        float w3 = W_head[(c0+kk+3)*96 + j];
        #pragma unroll
        for (int r = 0; r < 8; r++) {
            float4 v = *reinterpret_cast<const float4*>(&sf[g*8 + r][kk]);
            float a = acc[r];
            a = fmaf(v.x, w0, a); a = fmaf(v.y, w1, a);
            a = fmaf(v.z, w2, a); a = fmaf(v.w, w3, a);
            acc[r] = a;
        }
    }
    #pragma unroll
    for (int r = 0; r < 8; r++)
        g_part[((size_t)c*32 + g*8 + r)*PLEN + j] = acc[r];
}

// -------- K7: reduce partials, de-normalize, write output --------
__global__ void k_reduce(const float* __restrict__ b_head, float* __restrict__ out) {
    int bm = blockIdx.x, j = threadIdx.x;            // 32 blocks x 96 threads
    float acc = b_head[j];
    #pragma unroll 4
    for (int c = 0; c < 256; c++) acc += g_part[(c*32 + bm)*PLEN + j];
    out[bm*PLEN + j] = acc * g_std[bm] + g_mean[bm];
}

extern "C" void kernel_launch(void* const* d_in, const int* in_sizes, int n_in,
                              void* d_out, int out_size) {
    const float* x      = (const float*)d_in[0];
    const float* W_pe   = (const float*)d_in[1];
    const float* b_pe   = (const float*)d_in[2];
    const float* pos    = (const float*)d_in[3];
    const float* rms_w  = (const float*)d_in[4];
    const float* W_in   = (const float*)d_in[5];
    const float* conv_w = (const float*)d_in[6];
    const float* conv_b = (const float*)d_in[7];
    const float* W_xp   = (const float*)d_in[8];
    const float* W_dt   = (const float*)d_in[9];
    const float* b_dt   = (const float*)d_in[10];
    const float* A_log  = (const float*)d_in[11];
    const float* D_ssm  = (const float*)d_in[12];
    const float* W_out  = (const float*)d_in[13];
    const float* rmsf_w = (const float*)d_in[14];
    const float* ln_g   = (const float*)d_in[15];
    const float* ln_b   = (const float*)d_in[16];
    const float* W_head = (const float*)d_in[17];
    const float* b_head = (const float*)d_in[18];

    k_stats<<<BMSZ, 256>>>(x);
    k_embed<<<dim3(NP, BMSZ), DM>>>(x, W_pe, b_pe, pos);

    for (int l = 0; l < 2; l++) {
        k_in  <<<BMSZ*NP/32, 512>>>(rms_w + l*DM, W_in + l*DM*2*DI);
        k_cdbc<<<BMSZ*NP/16, 256>>>(conv_w + l*DI*4, conv_b + l*DI,
                                    W_xp + l*DI*40, W_dt + l*DTR*DI, b_dt + l*DI);
        k_scan<<<dim3(16, BMSZ), 256>>>(A_log + l*DI*DS, D_ssm + l*DI);
        k_out <<<BMSZ*NP/32, 512>>>(W_out + l*DI*DM);
    }

    k_head<<<KH/128, 384>>>(rmsf_w, ln_g, ln_b, W_head);
    k_reduce<<<BMSZ, PLEN>>>(b_head, (float*)d_out);
}